// round 6
// baseline (speedup 1.0000x reference)
#include <cuda_runtime.h>
#include <math.h>

// Problem constants (fixed by reference setup_inputs)
#define SN      10
#define ITERS   100
#define HWPIX   (128*128)
#define WDIM    128

// Global accumulators: [0]=n_neg [1]=n_pos [2]=sumsq_neg [3]=sumsq_posneg [4]=loss_pos
// Zero-initialized at load; the last finishing block resets them after use, so the
// invariant "zero on kernel entry" holds across graph replays.
__device__ double g_acc[5] = {0, 0, 0, 0, 0};
__device__ unsigned int g_ticket = 0;

// ---- packed f32x2 helpers (Blackwell sm_100+) ----
__device__ __forceinline__ unsigned long long f2_mul(unsigned long long a, unsigned long long b) {
    unsigned long long d;
    asm("mul.rn.f32x2 %0, %1, %2;" : "=l"(d) : "l"(a), "l"(b));
    return d;
}
__device__ __forceinline__ unsigned long long f2_fma(unsigned long long a, unsigned long long b, unsigned long long c) {
    unsigned long long d;
    asm("fma.rn.f32x2 %0, %1, %2, %3;" : "=l"(d) : "l"(a), "l"(b), "l"(c));
    return d;
}
__device__ __forceinline__ unsigned long long f2_pack(float lo, float hi) {
    unsigned long long d;
    asm("mov.b64 %0, {%1, %2};" : "=l"(d) : "f"(lo), "f"(hi));
    return d;
}
__device__ __forceinline__ void f2_unpack(unsigned long long v, float& lo, float& hi) {
    asm("mov.b64 {%0, %1}, %2;" : "=f"(lo), "=f"(hi) : "l"(v));
}

__global__ __launch_bounds__(128, 4) void ol_main_kernel(
    const float* __restrict__ outp_g,
    const float* __restrict__ tgt_g,
    const float* __restrict__ msk_g,
    float* __restrict__ result,
    int npix)
{
    int p = blockIdx.x * blockDim.x + threadIdx.x;

    float negf = 0.f, posf = 0.f, sumsq = 0.f, pnsq = 0.f, lp = 0.f;

    if (p < npix) {
        const int b  = p >> 14;            // HWPIX = 16384
        const int hw = p & (HWPIX - 1);
        const int h  = hw >> 7;
        const int w  = hw & (WDIM - 1);

        const float* outp = outp_g + (size_t)b * 36 * HWPIX + hw;
        const float* tgtp = tgt_g  + (size_t)b * 20 * HWPIX + hw;
        const float* mskp = msk_g  + (size_t)b * 10 * HWPIX + hw;

        // ---- pos/neg from mask ----
        float msum = 0.f;
        #pragma unroll
        for (int s = 0; s < SN; s++) msum += mskp[s * HWPIX];
        posf = (msum >= 1.0f) ? 1.0f : 0.0f;
        negf = 1.0f - posf;

        // ---- offsets: oy/ox for m=0..17; keep m<10, accumulate posneg sq for m>=10 ----
        // channel c(head,d,i,j) = head*18 + d*9 + i*3 + j ; m = head*9 + i*3 + j
        float oy[SN], ox[SN];
        #pragma unroll
        for (int m = 0; m < 18; m++) {
            const int head  = (m >= 9) ? 1 : 0;
            const int local = m - head * 9;
            const int i = local / 3;
            const int j = local - i * 3;
            const int cy = head * 18 + local;        // d=0
            const float vy = outp[cy * HWPIX];
            const float vx = outp[(cy + 9) * HWPIX]; // d=1
            sumsq += vy * vy + vx * vx;              // raw out^2 (all 36 channels)
            const float oyv = vy + (float)(i - 1) + (float)h;
            const float oxv = vx + (float)(j - 1) + (float)w;
            if (m < SN) { oy[m] = oyv; ox[m] = oxv; }
            else        { pnsq += oyv * oyv + oxv * oxv; }
        }

        // ---- cost rows -> row-stabilized Gibbs kernel K = exp(rmin - cost),
        //      packed as f32x2 pairs over m (layout serves both matvec passes) ----
        unsigned long long K2[SN][5];
        #pragma unroll
        for (int s = 0; s < SN; s++) {
            const float ty = tgtp[s * HWPIX];
            const float tx = tgtp[(SN + s) * HWPIX];
            float c[SN];
            float rm = 3.4e38f;
            #pragma unroll
            for (int m = 0; m < SN; m++) {
                c[m] = fabsf(ty - oy[m]) + fabsf(tx - ox[m]);
                rm = fminf(rm, c[m]);
            }
            #pragma unroll
            for (int k = 0; k < 5; k++)
                K2[s][k] = f2_pack(__expf(rm - c[2 * k]), __expf(rm - c[2 * k + 1]));
        }

        // ---- Sinkhorn in linear domain (equivalent to reference log-domain
        //      iterates up to a per-row dual shift that cancels in the assignment) ----
        if (msum >= 1.0f) {  // fully-negative pixels contribute 0 to loss_pos
            float a[SN];
            unsigned long long b2[5];
            #pragma unroll
            for (int k = 0; k < 5; k++) b2[k] = f2_pack(1.0f, 1.0f);  // v0 = 0
            #pragma unroll
            for (int s = 0; s < SN; s++) a[s] = 0.f;

            int it = 0;
            while (true) {
                // row pass: a[s] = 0.05 / sum_m K[s][m] * b[m]
                // convergence tracked in place against the previous iteration's a.
                bool conv = true;
                #pragma unroll
                for (int s = 0; s < SN; s++) {
                    unsigned long long acc = f2_mul(K2[s][0], b2[0]);
                    #pragma unroll
                    for (int k = 1; k < 5; k++) acc = f2_fma(K2[s][k], b2[k], acc);
                    float lo, hi; f2_unpack(acc, lo, hi);
                    const float anew = __fdividef(0.05f, lo + hi);
                    conv = conv && (fabsf(anew - a[s]) <= 2e-5f * anew);
                    a[s] = anew;
                }
                // col pass: b[m] = 0.05 / sum_s K[s][m] * a[s]
                unsigned long long acc2[5];
                {
                    const unsigned long long ab = f2_pack(a[0], a[0]);
                    #pragma unroll
                    for (int k = 0; k < 5; k++) acc2[k] = f2_mul(K2[0][k], ab);
                }
                #pragma unroll
                for (int s = 1; s < SN; s++) {
                    const unsigned long long ab = f2_pack(a[s], a[s]);
                    #pragma unroll
                    for (int k = 0; k < 5; k++) acc2[k] = f2_fma(K2[s][k], ab, acc2[k]);
                }
                #pragma unroll
                for (int k = 0; k < 5; k++) {
                    float lo, hi; f2_unpack(acc2[k], lo, hi);
                    b2[k] = f2_pack(__fdividef(0.05f, lo), __fdividef(0.05f, hi));
                }
                if (++it >= ITERS) break;
                // exit when a is stationary across one iteration for the whole warp
                // (contraction => distance-to-fixpoint bounded well inside 1e-3 budget)
                if (__all_sync(__activemask(), conv)) break;
            }

            // ---- loss_pos: assignment[s][m] = 20 * a[s] * K[s][m] * b[m];
            //      the weighted cost is the ORIGINAL cost c[s][m] (rmin - log K == c) ----
            #pragma unroll
            for (int s = 0; s < SN; s++) {
                const float ty = tgtp[s * HWPIX];
                const float tx = tgtp[(SN + s) * HWPIX];
                float inner = 0.f;
                #pragma unroll
                for (int k = 0; k < 5; k++) {
                    float k0, k1; f2_unpack(K2[s][k], k0, k1);
                    float q0, q1; f2_unpack(b2[k], q0, q1);
                    const float c0 = fabsf(ty - oy[2 * k])     + fabsf(tx - ox[2 * k]);
                    const float c1 = fabsf(ty - oy[2 * k + 1]) + fabsf(tx - ox[2 * k + 1]);
                    inner = fmaf(k0 * q0, c0, inner);
                    inner = fmaf(k1 * q1, c1, inner);
                }
                const float ms = mskp[s * HWPIX];  // reload (L2 hit)
                lp = fmaf(ms * a[s], inner, lp);
            }
            lp *= 20.0f;
        }
        sumsq *= negf;
        pnsq  *= posf;
    }

    // ---- warp reduce 5 quantities, one double atomic per warp each ----
    float vals[5] = { negf, posf, sumsq, pnsq, lp };
    #pragma unroll
    for (int k = 0; k < 5; k++) {
        float v = vals[k];
        #pragma unroll
        for (int off = 16; off; off >>= 1)
            v += __shfl_xor_sync(0xffffffffu, v, off);
        if ((threadIdx.x & 31) == 0)
            atomicAdd(&g_acc[k], (double)v);
    }

    // ---- fused finalize: last block computes the scalar result and resets state ----
    __syncthreads();
    if (threadIdx.x == 0) {
        __threadfence();  // make this block's atomics visible before taking a ticket
        const unsigned t = atomicAdd(&g_ticket, 1u);
        if (t == gridDim.x - 1) {
            __threadfence();  // acquire: all other blocks' atomics now visible
            const double n_neg = g_acc[0];
            const double n_pos = g_acc[1];
            const double loss_neg     = sqrt(g_acc[2]) / n_neg;
            const double loss_pos_neg = sqrt(g_acc[3]) / n_pos;
            result[0] = (float)((loss_neg + loss_pos_neg) * 100.0
                                + g_acc[4] / (n_pos + 0.0001));
            // reset for the next graph replay
            #pragma unroll
            for (int k = 0; k < 5; k++) g_acc[k] = 0.0;
            __threadfence();
            g_ticket = 0u;
        }
    }
}

extern "C" void kernel_launch(void* const* d_in, const int* in_sizes, int n_in,
                              void* d_out, int out_size) {
    const float* out_t  = (const float*)d_in[0];   // (B, 36, 128, 128)
    const float* target = (const float*)d_in[1];   // (B, 20, 128, 128)
    const float* mask   = (const float*)d_in[2];   // (B, 10, 128, 128)

    const int npix = in_sizes[2] / SN;             // B * H * W
    const int threads = 128;
    const int blocks = (npix + threads - 1) / threads;

    ol_main_kernel<<<blocks, threads>>>(out_t, target, mask, (float*)d_out, npix);
}

// round 7
// speedup vs baseline: 1.1778x; 1.1778x over previous
#include <cuda_runtime.h>
#include <math.h>

// Problem constants (fixed by reference setup_inputs)
#define SN      10
#define ITERS   100
#define HWPIX   (128*128)
#define WDIM    128

// Global accumulators: [0]=n_neg [1]=n_pos [2]=sumsq_neg [3]=sumsq_posneg [4]=loss_pos
// Zero-initialized at load; the last finishing block resets them after use, so the
// invariant "zero on kernel entry" holds across graph replays.
__device__ double g_acc[5] = {0, 0, 0, 0, 0};
__device__ unsigned int g_ticket = 0;

// ---- packed f32x2 helpers (Blackwell sm_100+) ----
__device__ __forceinline__ unsigned long long f2_mul(unsigned long long a, unsigned long long b) {
    unsigned long long d;
    asm("mul.rn.f32x2 %0, %1, %2;" : "=l"(d) : "l"(a), "l"(b));
    return d;
}
__device__ __forceinline__ unsigned long long f2_fma(unsigned long long a, unsigned long long b, unsigned long long c) {
    unsigned long long d;
    asm("fma.rn.f32x2 %0, %1, %2, %3;" : "=l"(d) : "l"(a), "l"(b), "l"(c));
    return d;
}
__device__ __forceinline__ unsigned long long f2_pack(float lo, float hi) {
    unsigned long long d;
    asm("mov.b64 %0, {%1, %2};" : "=l"(d) : "f"(lo), "f"(hi));
    return d;
}
__device__ __forceinline__ void f2_unpack(unsigned long long v, float& lo, float& hi) {
    asm("mov.b64 {%0, %1}, %2;" : "=f"(lo), "=f"(hi) : "l"(v));
}

// 3 CTAs/SM -> 170-reg ceiling: above the ~120-reg hot-loop live set (no loop
// spills, unlike the 128-reg cap that regressed R5), 50% more warps than the
// unconstrained 254-reg / 2-CTA configuration.
__global__ __launch_bounds__(128, 3) void ol_main_kernel(
    const float* __restrict__ outp_g,
    const float* __restrict__ tgt_g,
    const float* __restrict__ msk_g,
    float* __restrict__ result,
    int npix)
{
    int p = blockIdx.x * blockDim.x + threadIdx.x;

    float negf = 0.f, posf = 0.f, sumsq = 0.f, pnsq = 0.f, lp = 0.f;

    if (p < npix) {
        const int b  = p >> 14;            // HWPIX = 16384
        const int hw = p & (HWPIX - 1);
        const int h  = hw >> 7;
        const int w  = hw & (WDIM - 1);

        const float* outp = outp_g + (size_t)b * 36 * HWPIX + hw;
        const float* tgtp = tgt_g  + (size_t)b * 20 * HWPIX + hw;
        const float* mskp = msk_g  + (size_t)b * 10 * HWPIX + hw;

        // ---- pos/neg from mask ----
        float msum = 0.f;
        #pragma unroll
        for (int s = 0; s < SN; s++) msum += mskp[s * HWPIX];
        posf = (msum >= 1.0f) ? 1.0f : 0.0f;
        negf = 1.0f - posf;

        // ---- offsets: oy/ox for m=0..17; keep m<10, accumulate posneg sq for m>=10 ----
        // channel c(head,d,i,j) = head*18 + d*9 + i*3 + j ; m = head*9 + i*3 + j
        float oy[SN], ox[SN];
        #pragma unroll
        for (int m = 0; m < 18; m++) {
            const int head  = (m >= 9) ? 1 : 0;
            const int local = m - head * 9;
            const int i = local / 3;
            const int j = local - i * 3;
            const int cy = head * 18 + local;        // d=0
            const float vy = outp[cy * HWPIX];
            const float vx = outp[(cy + 9) * HWPIX]; // d=1
            sumsq += vy * vy + vx * vx;              // raw out^2 (all 36 channels)
            const float oyv = vy + (float)(i - 1) + (float)h;
            const float oxv = vx + (float)(j - 1) + (float)w;
            if (m < SN) { oy[m] = oyv; ox[m] = oxv; }
            else        { pnsq += oyv * oyv + oxv * oxv; }
        }

        // ---- cost rows -> row-stabilized Gibbs kernel K = exp(rmin - cost),
        //      packed as f32x2 pairs over m (layout serves both matvec passes) ----
        unsigned long long K2[SN][5];
        #pragma unroll
        for (int s = 0; s < SN; s++) {
            const float ty = tgtp[s * HWPIX];
            const float tx = tgtp[(SN + s) * HWPIX];
            float c[SN];
            float rm = 3.4e38f;
            #pragma unroll
            for (int m = 0; m < SN; m++) {
                c[m] = fabsf(ty - oy[m]) + fabsf(tx - ox[m]);
                rm = fminf(rm, c[m]);
            }
            #pragma unroll
            for (int k = 0; k < 5; k++)
                K2[s][k] = f2_pack(__expf(rm - c[2 * k]), __expf(rm - c[2 * k + 1]));
        }

        // ---- Sinkhorn in linear domain (equivalent to reference log-domain
        //      iterates up to a per-row dual shift that cancels in the assignment) ----
        if (msum >= 1.0f) {  // fully-negative pixels contribute 0 to loss_pos
            float a[SN];
            unsigned long long b2[5];
            #pragma unroll
            for (int k = 0; k < 5; k++) b2[k] = f2_pack(1.0f, 1.0f);  // v0 = 0
            #pragma unroll
            for (int s = 0; s < SN; s++) a[s] = 0.f;

            int it = 0;
            while (true) {
                // row pass: a[s] = 0.05 / sum_m K[s][m] * b[m]
                // convergence tracked in place against the previous iteration's a.
                bool conv = true;
                #pragma unroll
                for (int s = 0; s < SN; s++) {
                    unsigned long long acc = f2_mul(K2[s][0], b2[0]);
                    #pragma unroll
                    for (int k = 1; k < 5; k++) acc = f2_fma(K2[s][k], b2[k], acc);
                    float lo, hi; f2_unpack(acc, lo, hi);
                    const float anew = __fdividef(0.05f, lo + hi);
                    conv = conv && (fabsf(anew - a[s]) <= 1e-4f * anew);
                    a[s] = anew;
                }
                // col pass: b[m] = 0.05 / sum_s K[s][m] * a[s]
                unsigned long long acc2[5];
                {
                    const unsigned long long ab = f2_pack(a[0], a[0]);
                    #pragma unroll
                    for (int k = 0; k < 5; k++) acc2[k] = f2_mul(K2[0][k], ab);
                }
                #pragma unroll
                for (int s = 1; s < SN; s++) {
                    const unsigned long long ab = f2_pack(a[s], a[s]);
                    #pragma unroll
                    for (int k = 0; k < 5; k++) acc2[k] = f2_fma(K2[s][k], ab, acc2[k]);
                }
                #pragma unroll
                for (int k = 0; k < 5; k++) {
                    float lo, hi; f2_unpack(acc2[k], lo, hi);
                    b2[k] = f2_pack(__fdividef(0.05f, lo), __fdividef(0.05f, hi));
                }
                if (++it >= ITERS) break;
                // exit when a is stationary across one iteration for the whole warp
                // (contraction => distance-to-fixpoint bounded well inside the 1e-3
                // budget; measured rel_err has been insensitive to this eps from
                // 1e-6 through 2e-5, indicating large remaining headroom)
                if (__all_sync(__activemask(), conv)) break;
            }

            // ---- loss_pos: assignment[s][m] = 20 * a[s] * K[s][m] * b[m];
            //      the weighted cost is the ORIGINAL cost c[s][m] (rmin - log K == c) ----
            #pragma unroll
            for (int s = 0; s < SN; s++) {
                const float ty = tgtp[s * HWPIX];
                const float tx = tgtp[(SN + s) * HWPIX];
                float inner = 0.f;
                #pragma unroll
                for (int k = 0; k < 5; k++) {
                    float k0, k1; f2_unpack(K2[s][k], k0, k1);
                    float q0, q1; f2_unpack(b2[k], q0, q1);
                    const float c0 = fabsf(ty - oy[2 * k])     + fabsf(tx - ox[2 * k]);
                    const float c1 = fabsf(ty - oy[2 * k + 1]) + fabsf(tx - ox[2 * k + 1]);
                    inner = fmaf(k0 * q0, c0, inner);
                    inner = fmaf(k1 * q1, c1, inner);
                }
                const float ms = mskp[s * HWPIX];  // reload (L2 hit)
                lp = fmaf(ms * a[s], inner, lp);
            }
            lp *= 20.0f;
        }
        sumsq *= negf;
        pnsq  *= posf;
    }

    // ---- warp reduce 5 quantities, one double atomic per warp each ----
    float vals[5] = { negf, posf, sumsq, pnsq, lp };
    #pragma unroll
    for (int k = 0; k < 5; k++) {
        float v = vals[k];
        #pragma unroll
        for (int off = 16; off; off >>= 1)
            v += __shfl_xor_sync(0xffffffffu, v, off);
        if ((threadIdx.x & 31) == 0)
            atomicAdd(&g_acc[k], (double)v);
    }

    // ---- fused finalize: last block computes the scalar result and resets state ----
    __syncthreads();
    if (threadIdx.x == 0) {
        __threadfence();  // make this block's atomics visible before taking a ticket
        const unsigned t = atomicAdd(&g_ticket, 1u);
        if (t == gridDim.x - 1) {
            __threadfence();  // acquire: all other blocks' atomics now visible
            const double n_neg = g_acc[0];
            const double n_pos = g_acc[1];
            const double loss_neg     = sqrt(g_acc[2]) / n_neg;
            const double loss_pos_neg = sqrt(g_acc[3]) / n_pos;
            result[0] = (float)((loss_neg + loss_pos_neg) * 100.0
                                + g_acc[4] / (n_pos + 0.0001));
            // reset for the next graph replay
            #pragma unroll
            for (int k = 0; k < 5; k++) g_acc[k] = 0.0;
            __threadfence();
            g_ticket = 0u;
        }
    }
}

extern "C" void kernel_launch(void* const* d_in, const int* in_sizes, int n_in,
                              void* d_out, int out_size) {
    const float* out_t  = (const float*)d_in[0];   // (B, 36, 128, 128)
    const float* target = (const float*)d_in[1];   // (B, 20, 128, 128)
    const float* mask   = (const float*)d_in[2];   // (B, 10, 128, 128)

    const int npix = in_sizes[2] / SN;             // B * H * W
    const int threads = 128;
    const int blocks = (npix + threads - 1) / threads;

    ol_main_kernel<<<blocks, threads>>>(out_t, target, mask, (float*)d_out, npix);
}